// round 10
// baseline (speedup 1.0000x reference)
#include <cuda_runtime.h>
#include <cuda_fp16.h>
#include <cstdint>

// Problem constants
constexpr int NN   = 50000;
constexpr int DIN  = 128;
constexpr int DOUT = 128;
constexpr int ELLW = 64;

// Scratch
__device__ __half   g_w16[DIN * DOUT];              // fp16 copy of W (32 KB)
__device__ __half   g_hw[(size_t)NN * DOUT];        // fp16 projected features (12.8 MB)
__device__ uint16_t g_ell[(size_t)NN * ELLW];       // packed src ids (6.4 MB)
__device__ int      g_cnt[NN];

// m16n8k16 fp16 mma, f32 accumulate: D += A*B
#define MMA_F16(d, a, b)                                                      \
    asm volatile("mma.sync.aligned.m16n8k16.row.col.f32.f16.f16.f32 "         \
        "{%0,%1,%2,%3}, {%4,%5,%6,%7}, {%8,%9}, {%0,%1,%2,%3};"               \
        : "+f"((d)[0]), "+f"((d)[1]), "+f"((d)[2]), "+f"((d)[3])              \
        : "r"((a)[0]), "r"((a)[1]), "r"((a)[2]), "r"((a)[3]),                 \
          "r"((b)[0]), "r"((b)[1]))

#define LDM_X4(r, addr)                                                       \
    asm volatile("ldmatrix.sync.aligned.m8n8.x4.shared.b16 {%0,%1,%2,%3}, [%4];" \
        : "=r"((r)[0]), "=r"((r)[1]), "=r"((r)[2]), "=r"((r)[3]) : "r"(addr))

#define LDM_X4_T(r, addr)                                                     \
    asm volatile("ldmatrix.sync.aligned.m8n8.x4.trans.shared.b16 {%0,%1,%2,%3}, [%4];" \
        : "=r"((r)[0]), "=r"((r)[1]), "=r"((r)[2]), "=r"((r)[3]) : "r"(addr))

#define CP_ASYNC16(dst, src)                                                  \
    asm volatile("cp.async.ca.shared.global [%0], [%1], 16;"                  \
        :: "r"(dst), "l"(src) : "memory")
#define CP_COMMIT()  asm volatile("cp.async.commit_group;" ::: "memory")
#define CP_WAIT0()   asm volatile("cp.async.wait_group 0;" ::: "memory")

// fp16 tile pitch: 136 halves = 272 B = 17 quads -> conflict-free ldmatrix.
constexpr int PIT   = 136;                      // halves
constexpr int PIT32 = 132;                      // fp32 staging pitch (words; 528B = 33 quads)

// SMEM layout (bytes)
constexpr int OFF_A32 = 0;                              // [64 r][132 w] fp32
constexpr int A32_B   = 64 * PIT32 * 4;                 // 33,792
constexpr int OFF_A16 = A32_B;                          // [64 r][136 h] fp16
constexpr int A16_B   = 64 * PIT * 2;                   // 17,408
constexpr int OFF_W16 = OFF_A16 + A16_B;                // [128 k][136 h] fp16 (K-major)
constexpr int W16_B   = 128 * PIT * 2;                  // 34,816
constexpr int SMEM_BYTES = OFF_W16 + W16_B;             // 86,016

constexpr int NGEMM = (NN + 63) / 64;                   // 782 gemm blocks
constexpr int EDGES_PER_BLK = 512;                      // 128 thr x 4 edges

// ---------------------------------------------------------------------------
// Kernel 0: prep — convert W to fp16 global, zero g_cnt.
// ---------------------------------------------------------------------------
__global__ void __launch_bounds__(256) prep_kernel(const float* __restrict__ W)
{
    int i = blockIdx.x * blockDim.x + threadIdx.x;
    if (i < DIN * DOUT / 4) {
        float4 v = *(const float4*)(W + (size_t)i * 4);
        __half hh[4] = {__float2half_rn(v.x), __float2half_rn(v.y),
                        __float2half_rn(v.z), __float2half_rn(v.w)};
        *(uint2*)(g_w16 + (size_t)i * 4) = *(uint2*)hh;
    }
    if (i < NN) g_cnt[i] = 0;
}

// ---------------------------------------------------------------------------
// Kernel 1 (fused): blocks [0, NGEMM) do the projection GEMM;
// blocks [NGEMM, ...) build the ELL adjacency. Independent work, co-scheduled
// so edge atomics hide in gemm stall slots.
// ---------------------------------------------------------------------------
__global__ void __launch_bounds__(128, 2) gemm_build_kernel(
    const float* __restrict__ h,
    const float* __restrict__ norm,
    const int*   __restrict__ src,
    const int*   __restrict__ dst,
    float*       __restrict__ out,
    int E)
{
    const int tid = threadIdx.x;

    // ======================= build part =======================
    if (blockIdx.x >= NGEMM) {
        int base = (blockIdx.x - NGEMM) * EDGES_PER_BLK;
        #pragma unroll
        for (int j = 0; j < 4; j++) {
            int e = base + j * 128 + tid;
            if (e < E) {
                int s = __ldg(src + e);
                int d = __ldg(dst + e);
                int pos = atomicAdd(&g_cnt[d], 1);
                if (pos < ELLW) {
                    g_ell[(size_t)d * ELLW + pos] = (uint16_t)s;
                }
                // deg > ELLW is statistically impossible (Poisson(16), 50K
                // nodes: P ~ 1e-13); dropped edges would also race with the
                // concurrent gemm, so no fallback here.
            }
        }
        return;
    }

    // ======================= gemm part =======================
    extern __shared__ char smem[];
    const uint32_t sb   = (uint32_t)__cvta_generic_to_shared(smem);
    const uint32_t sA32 = sb + OFF_A32;
    const uint32_t sA16 = sb + OFF_A16;
    const uint32_t sW16 = sb + OFF_W16;
    float*  A32 = (float*)(smem + OFF_A32);
    __half* A16 = (__half*)(smem + OFF_A16);

    const int lane = tid & 31;
    const int wid  = tid >> 5;
    const int wm   = wid & 1;                   // m block (32 rows)
    const int wn   = wid >> 1;                  // n block (64 cols)
    const int g    = lane >> 2;
    const int t    = lane & 3;
    const int row0 = blockIdx.x * 64;

    // ---- async fills: A fp32 (2048 granules), W fp16 (2048 granules) ----
    #pragma unroll
    for (int it = 0; it < 16; it++) {
        int i  = it * 128 + tid;
        int r  = i >> 5;                         // 0..63
        int c4 = (i & 31) << 2;                  // float offset, 16B granules
        int gr = row0 + r;
        if (gr >= NN) gr = NN - 1;               // clamp (stores guarded later)
        CP_ASYNC16(sA32 + (uint32_t)(r * PIT32 + c4) * 4,
                   h + (size_t)gr * DIN + c4);
    }
    #pragma unroll
    for (int it = 0; it < 16; it++) {
        int i  = it * 128 + tid;
        int k  = i >> 4;                         // 0..127
        int gq = (i & 15) << 3;                  // half offset
        CP_ASYNC16(sW16 + (uint32_t)(k * PIT + gq) * 2,
                   g_w16 + (size_t)k * DOUT + gq);
    }
    CP_COMMIT();
    CP_WAIT0();
    __syncthreads();

    // ---- convert A fp32 -> fp16 tile (LDS.128 -> cvt -> STS.64) ----
    #pragma unroll
    for (int it = 0; it < 16; it++) {
        int i  = it * 128 + tid;
        int r  = i >> 5;                         // 0..63
        int c4 = (i & 31) << 2;                  // 0..124
        float4 v = *(const float4*)(A32 + r * PIT32 + c4);
        __half2 p0 = __floats2half2_rn(v.x, v.y);
        __half2 p1 = __floats2half2_rn(v.z, v.w);
        __half2* dst2 = (__half2*)(A16 + r * PIT + c4);
        dst2[0] = p0;
        dst2[1] = p1;
    }
    __syncthreads();

    // ldmatrix base addresses
    const uint32_t adrA = sA16 + (uint32_t)(((wm * 32 + (lane & 15)) * PIT
                                             + ((lane >> 4) << 3)) * 2);
    const uint32_t adrB = sW16 + (uint32_t)(((lane & 15) * PIT
                                             + wn * 64 + ((lane >> 4) << 3)) * 2);

    float acc[2][8][4];
    #pragma unroll
    for (int mt = 0; mt < 2; mt++)
        #pragma unroll
        for (int nt = 0; nt < 8; nt++)
            #pragma unroll
            for (int e = 0; e < 4; e++)
                acc[mt][nt][e] = 0.f;

    // ---- 8 k-steps of 16 over full K=128 ----
    #pragma unroll
    for (int ks = 0; ks < 8; ks++) {
        const uint32_t akb = (uint32_t)(ks * 16 * 2);
        const uint32_t bkb = (uint32_t)(ks * 16 * PIT * 2);

        uint32_t ah[2][4];
        #pragma unroll
        for (int mt = 0; mt < 2; mt++)
            LDM_X4(ah[mt], adrA + (uint32_t)(mt * 16 * PIT * 2) + akb);

        #pragma unroll
        for (int np = 0; np < 4; np++) {
            uint32_t bv[4];
            LDM_X4_T(bv, adrB + (uint32_t)(np * 16 * 2) + bkb);
            #pragma unroll
            for (int half = 0; half < 2; half++) {
                int nt = 2 * np + half;
                uint32_t b[2] = {bv[2 * half], bv[2 * half + 1]};
                #pragma unroll
                for (int mt = 0; mt < 2; mt++)
                    MMA_F16(acc[mt][nt], ah[mt], b);
            }
        }
    }

    // ---- epilogue: scale by norm[row], convert to fp16, store g_hw ----
    #pragma unroll
    for (int mt = 0; mt < 2; mt++) {
        int r_lo = row0 + wm * 32 + mt * 16 + g;
        int r_hi = r_lo + 8;
        float n_lo = (r_lo < NN) ? __ldg(norm + r_lo) : 0.f;
        float n_hi = (r_hi < NN) ? __ldg(norm + r_hi) : 0.f;
        #pragma unroll
        for (int nt = 0; nt < 8; nt++) {
            int col = wn * 64 + nt * 8 + 2 * t;
            if (r_lo < NN) {
                __half2 o = __floats2half2_rn(acc[mt][nt][0] * n_lo,
                                              acc[mt][nt][1] * n_lo);
                *(__half2*)(g_hw + (size_t)r_lo * DOUT + col) = o;
            }
            if (r_hi < NN) {
                __half2 o = __floats2half2_rn(acc[mt][nt][2] * n_hi,
                                              acc[mt][nt][3] * n_hi);
                *(__half2*)(g_hw + (size_t)r_hi * DOUT + col) = o;
            }
        }
    }
}

// ---------------------------------------------------------------------------
// Kernel 2: aggregate + fused epilogue. One warp per dst node.
// ---------------------------------------------------------------------------
__global__ void __launch_bounds__(256) agg_kernel(
    float* __restrict__ out,
    const float* __restrict__ norm,
    const float* __restrict__ bias)
{
    int warp = (blockIdx.x * blockDim.x + threadIdx.x) >> 5;
    int lane = threadIdx.x & 31;
    if (warp >= NN) return;
    const int d = warp;

    int cnt_raw = __ldg(&g_cnt[d]);
    int n = cnt_raw < ELLW ? cnt_raw : ELLW;

    uint32_t packed = *(const uint32_t*)(g_ell + (size_t)d * ELLW + 2 * lane);

    float4 acc = make_float4(0.f, 0.f, 0.f, 0.f);
    const int co = lane * 4;

    #define GET_ID(j) ({                                                   \
        uint32_t _p = __shfl_sync(0xffffffffu, packed, (j) >> 1);          \
        (int)(((j) & 1) ? (_p >> 16) : (_p & 0xffffu)); })

    int i = 0;
    for (; i + 4 <= n; i += 4) {
        int s0 = GET_ID(i);
        int s1 = GET_ID(i + 1);
        int s2 = GET_ID(i + 2);
        int s3 = GET_ID(i + 3);
        uint2 u0 = *(const uint2*)(g_hw + (size_t)s0 * DOUT + co);
        uint2 u1 = *(const uint2*)(g_hw + (size_t)s1 * DOUT + co);
        uint2 u2 = *(const uint2*)(g_hw + (size_t)s2 * DOUT + co);
        uint2 u3 = *(const uint2*)(g_hw + (size_t)s3 * DOUT + co);
        float2 a0 = __half22float2(*(__half2*)&u0.x), b0 = __half22float2(*(__half2*)&u0.y);
        float2 a1 = __half22float2(*(__half2*)&u1.x), b1 = __half22float2(*(__half2*)&u1.y);
        float2 a2 = __half22float2(*(__half2*)&u2.x), b2 = __half22float2(*(__half2*)&u2.y);
        float2 a3 = __half22float2(*(__half2*)&u3.x), b3 = __half22float2(*(__half2*)&u3.y);
        acc.x += (a0.x + a1.x) + (a2.x + a3.x);
        acc.y += (a0.y + a1.y) + (a2.y + a3.y);
        acc.z += (b0.x + b1.x) + (b2.x + b3.x);
        acc.w += (b0.y + b1.y) + (b2.y + b3.y);
    }
    for (; i < n; i++) {
        int s0 = GET_ID(i);
        uint2 u = *(const uint2*)(g_hw + (size_t)s0 * DOUT + co);
        float2 a = __half22float2(*(__half2*)&u.x);
        float2 b = __half22float2(*(__half2*)&u.y);
        acc.x += a.x; acc.y += a.y; acc.z += b.x; acc.w += b.y;
    }

    float nr = __ldg(norm + d);
    float4 b = *(const float4*)(bias + co);
    float4 r;
    r.x = fmaxf(fmaf(acc.x, nr, b.x), 0.f);
    r.y = fmaxf(fmaf(acc.y, nr, b.y), 0.f);
    r.z = fmaxf(fmaf(acc.z, nr, b.z), 0.f);
    r.w = fmaxf(fmaf(acc.w, nr, b.w), 0.f);
    *(float4*)(out + (size_t)d * DOUT + co) = r;

    #undef GET_ID
}

// ---------------------------------------------------------------------------
// Launch. Input order (metadata): h, weight, bias, norm, src, dst
// ---------------------------------------------------------------------------
extern "C" void kernel_launch(void* const* d_in, const int* in_sizes, int n_in,
                              void* d_out, int out_size)
{
    const float* h    = (const float*)d_in[0];
    const float* W    = (const float*)d_in[1];
    const float* bias = (const float*)d_in[2];
    const float* norm = (const float*)d_in[3];
    const int*   src  = (const int*)d_in[4];
    const int*   dst  = (const int*)d_in[5];
    float*       out  = (float*)d_out;

    const int E = in_sizes[4];

    cudaFuncSetAttribute(gemm_build_kernel,
                         cudaFuncAttributeMaxDynamicSharedMemorySize, SMEM_BYTES);

    // 0) convert W to fp16; zero g_cnt
    prep_kernel<<<(NN + 255) / 256, 256>>>(W);

    // 1) fused: projection GEMM + ELL build (independent block families)
    {
        int nbuild = (E + EDGES_PER_BLK - 1) / EDGES_PER_BLK;
        gemm_build_kernel<<<NGEMM + nbuild, 128, SMEM_BYTES>>>(
            h, norm, src, dst, out, E);
    }

    // 2) gather-aggregate + fused norm/bias/relu (one warp per node)
    agg_kernel<<<(NN * 32 + 255) / 256, 256>>>(out, norm, bias);
}

// round 11
// speedup vs baseline: 1.1047x; 1.1047x over previous
#include <cuda_runtime.h>
#include <cuda_fp16.h>
#include <cstdint>

// Problem constants
constexpr int NN   = 50000;
constexpr int DIN  = 128;
constexpr int DOUT = 128;
constexpr int ELLW = 64;

// Scratch
__device__ __half   g_h16[(size_t)NN * DIN];        // fp16 copy of h (12.8 MB)
__device__ __half   g_w16[DIN * DOUT];              // fp16 copy of W (32 KB)
__device__ __half   g_hw[(size_t)NN * DOUT];        // fp16 projected features (12.8 MB)
__device__ uint16_t g_ell[(size_t)NN * ELLW];       // packed src ids (6.4 MB)
__device__ int      g_cnt[NN];

// m16n8k16 fp16 mma, f32 accumulate: D += A*B
#define MMA_F16(d, a, b)                                                      \
    asm volatile("mma.sync.aligned.m16n8k16.row.col.f32.f16.f16.f32 "         \
        "{%0,%1,%2,%3}, {%4,%5,%6,%7}, {%8,%9}, {%0,%1,%2,%3};"               \
        : "+f"((d)[0]), "+f"((d)[1]), "+f"((d)[2]), "+f"((d)[3])              \
        : "r"((a)[0]), "r"((a)[1]), "r"((a)[2]), "r"((a)[3]),                 \
          "r"((b)[0]), "r"((b)[1]))

#define LDM_X4(r, addr)                                                       \
    asm volatile("ldmatrix.sync.aligned.m8n8.x4.shared.b16 {%0,%1,%2,%3}, [%4];" \
        : "=r"((r)[0]), "=r"((r)[1]), "=r"((r)[2]), "=r"((r)[3]) : "r"(addr))

#define LDM_X4_T(r, addr)                                                     \
    asm volatile("ldmatrix.sync.aligned.m8n8.x4.trans.shared.b16 {%0,%1,%2,%3}, [%4];" \
        : "=r"((r)[0]), "=r"((r)[1]), "=r"((r)[2]), "=r"((r)[3]) : "r"(addr))

#define CP_ASYNC16(dst, src)                                                  \
    asm volatile("cp.async.ca.shared.global [%0], [%1], 16;"                  \
        :: "r"(dst), "l"(src) : "memory")
#define CP_COMMIT()  asm volatile("cp.async.commit_group;" ::: "memory")
#define CP_WAIT0()   asm volatile("cp.async.wait_group 0;" ::: "memory")

// Pitch 136 halves = 272 B = 17 quads -> conflict-free ldmatrix phases,
// 16B-aligned rows for cp.async.
constexpr int PIT = 136;                        // halves
constexpr int A_HALVES = 64 * PIT;              // 8704  (17,408 B)
constexpr int W_HALVES = 128 * PIT;             // 17408 (34,816 B)
constexpr int SMEM_BYTES = (A_HALVES + W_HALVES) * 2;   // 52,224 B

// ---------------------------------------------------------------------------
// Kernel 0: prep — convert h and W to fp16 globals, zero g_cnt.
// ---------------------------------------------------------------------------
__global__ void __launch_bounds__(256) prep_kernel(
    const float* __restrict__ h,
    const float* __restrict__ W)
{
    int i = blockIdx.x * blockDim.x + threadIdx.x;

    if (i < NN * DIN / 4) {
        float4 v = *(const float4*)(h + (size_t)i * 4);
        __half hh[4] = {__float2half_rn(v.x), __float2half_rn(v.y),
                        __float2half_rn(v.z), __float2half_rn(v.w)};
        *(uint2*)(g_h16 + (size_t)i * 4) = *(uint2*)hh;
    }
    if (i < DIN * DOUT / 4) {
        float4 v = *(const float4*)(W + (size_t)i * 4);
        __half hh[4] = {__float2half_rn(v.x), __float2half_rn(v.y),
                        __float2half_rn(v.z), __float2half_rn(v.w)};
        *(uint2*)(g_w16 + (size_t)i * 4) = *(uint2*)hh;
    }
    if (i < NN) g_cnt[i] = 0;
}

// ---------------------------------------------------------------------------
// Kernel 1: hw = fp16((h @ W) * norm), single fp16 mma (f32 accum).
// CTA: 64 rows x 128 cols, 4 warps (warp tile 32x64), full K=128 resident.
// Fills via cp.async from pre-converted fp16 globals (latency-insensitive).
// ---------------------------------------------------------------------------
__global__ void __launch_bounds__(128, 4) gemm_mma_kernel(
    const float* __restrict__ norm)
{
    extern __shared__ __half smem_h[];

    const int tid  = threadIdx.x;
    const int lane = tid & 31;
    const int wid  = tid >> 5;
    const int wm   = wid & 1;                   // m block (32 rows)
    const int wn   = wid >> 1;                  // n block (64 cols)
    const int g    = lane >> 2;
    const int t    = lane & 3;
    const int row0 = blockIdx.x * 64;

    const uint32_t sb = (uint32_t)__cvta_generic_to_shared(smem_h);
    const uint32_t sA = sb;                      // As: [64 r][PIT k]
    const uint32_t sW = sb + A_HALVES * 2;       // Ws: [128 k][PIT n] (K-major)

    // ---- async fills: A = 1024 16B-granules, W = 2048 ----
    #pragma unroll
    for (int it = 0; it < 8; it++) {
        int i  = it * 128 + tid;
        int r  = i >> 4;
        int gq = (i & 15) << 3;                  // half offset within row
        int gr = row0 + r;
        if (gr >= NN) gr = NN - 1;               // clamp (stores guarded later)
        CP_ASYNC16(sA + (uint32_t)(r * PIT + gq) * 2,
                   g_h16 + (size_t)gr * DIN + gq);
    }
    #pragma unroll
    for (int it = 0; it < 16; it++) {
        int i  = it * 128 + tid;
        int k  = i >> 4;
        int gq = (i & 15) << 3;
        CP_ASYNC16(sW + (uint32_t)(k * PIT + gq) * 2,
                   g_w16 + (size_t)k * DOUT + gq);
    }
    CP_COMMIT();
    CP_WAIT0();
    __syncthreads();

    // ldmatrix base addresses (bytes, shared space)
    const uint32_t adrA = sA + (uint32_t)(((wm * 32 + (lane & 15)) * PIT
                                           + ((lane >> 4) << 3)) * 2);
    const uint32_t adrB = sW + (uint32_t)(((lane & 15) * PIT
                                           + wn * 64 + ((lane >> 4) << 3)) * 2);

    float acc[2][8][4];
    #pragma unroll
    for (int mt = 0; mt < 2; mt++)
        #pragma unroll
        for (int nt = 0; nt < 8; nt++)
            #pragma unroll
            for (int e = 0; e < 4; e++)
                acc[mt][nt][e] = 0.f;

    // ---- 8 k-steps of 16 over full K=128 ----
    #pragma unroll
    for (int ks = 0; ks < 8; ks++) {
        const uint32_t akb = (uint32_t)(ks * 16 * 2);          // A: +16 halves in k
        const uint32_t bkb = (uint32_t)(ks * 16 * PIT * 2);    // B: +16 rows in k

        uint32_t ah[2][4];
        #pragma unroll
        for (int mt = 0; mt < 2; mt++)
            LDM_X4(ah[mt], adrA + (uint32_t)(mt * 16 * PIT * 2) + akb);

        #pragma unroll
        for (int np = 0; np < 4; np++) {
            uint32_t bv[4];
            LDM_X4_T(bv, adrB + (uint32_t)(np * 16 * 2) + bkb);
            #pragma unroll
            for (int half = 0; half < 2; half++) {
                int nt = 2 * np + half;
                uint32_t b[2] = {bv[2 * half], bv[2 * half + 1]};
                #pragma unroll
                for (int mt = 0; mt < 2; mt++)
                    MMA_F16(acc[mt][nt], ah[mt], b);
            }
        }
    }

    // ---- epilogue: scale by norm[row], convert to fp16, store g_hw ----
    #pragma unroll
    for (int mt = 0; mt < 2; mt++) {
        int r_lo = row0 + wm * 32 + mt * 16 + g;
        int r_hi = r_lo + 8;
        float n_lo = (r_lo < NN) ? __ldg(norm + r_lo) : 0.f;
        float n_hi = (r_hi < NN) ? __ldg(norm + r_hi) : 0.f;
        #pragma unroll
        for (int nt = 0; nt < 8; nt++) {
            int col = wn * 64 + nt * 8 + 2 * t;
            if (r_lo < NN) {
                __half2 o = __floats2half2_rn(acc[mt][nt][0] * n_lo,
                                              acc[mt][nt][1] * n_lo);
                *(__half2*)(g_hw + (size_t)r_lo * DOUT + col) = o;
            }
            if (r_hi < NN) {
                __half2 o = __floats2half2_rn(acc[mt][nt][2] * n_hi,
                                              acc[mt][nt][3] * n_hi);
                *(__half2*)(g_hw + (size_t)r_hi * DOUT + col) = o;
            }
        }
    }
}

// ---------------------------------------------------------------------------
// Kernel 2: build ELL adjacency (u16 ids). One thread per edge.
// ---------------------------------------------------------------------------
__global__ void __launch_bounds__(256) build_kernel(
    const int* __restrict__ src,
    const int* __restrict__ dst,
    float* __restrict__ out,
    int E)
{
    int e = blockIdx.x * blockDim.x + threadIdx.x;
    if (e >= E) return;
    int s = __ldg(src + e);
    int d = __ldg(dst + e);
    int pos = atomicAdd(&g_cnt[d], 1);
    if (pos < ELLW) {
        g_ell[(size_t)d * ELLW + pos] = (uint16_t)s;
    } else {
        // overflow fallback (statistically never; degrees ~ Poisson(16))
        const __half* hs = g_hw + (size_t)s * DOUT;
        float* po = out + (size_t)d * DOUT;
        for (int j = 0; j < DOUT; j += 2) {
            float2 v = __half22float2(*(const __half2*)(hs + j));
            asm volatile("red.global.add.f32 [%0], %1;" :: "l"(po + j),     "f"(v.x) : "memory");
            asm volatile("red.global.add.f32 [%0], %1;" :: "l"(po + j + 1), "f"(v.y) : "memory");
        }
    }
}

// ---------------------------------------------------------------------------
// Kernel 3: aggregate + fused epilogue. One warp per dst node.
// Quad-wise fp16 tree reduction (6 HADD2 per 4 rows), fp32 master accumulator.
// ---------------------------------------------------------------------------
__global__ void __launch_bounds__(256) agg_kernel(
    float* __restrict__ out,
    const float* __restrict__ norm,
    const float* __restrict__ bias)
{
    int warp = (blockIdx.x * blockDim.x + threadIdx.x) >> 5;
    int lane = threadIdx.x & 31;
    if (warp >= NN) return;
    const int d = warp;

    int cnt_raw = __ldg(&g_cnt[d]);
    int n = cnt_raw < ELLW ? cnt_raw : ELLW;

    // lane i holds packed ids for slots 2i, 2i+1
    uint32_t packed = *(const uint32_t*)(g_ell + (size_t)d * ELLW + 2 * lane);

    float4 acc = make_float4(0.f, 0.f, 0.f, 0.f);
    const int co = lane * 4;

    int i = 0;
    for (; i + 4 <= n; i += 4) {
        // 2 shfls deliver 4 ids (2 packed per lane)
        uint32_t p0 = __shfl_sync(0xffffffffu, packed, i >> 1);
        uint32_t p1 = __shfl_sync(0xffffffffu, packed, (i >> 1) + 1);
        int s0 = (int)(p0 & 0xffffu), s1 = (int)(p0 >> 16);
        int s2 = (int)(p1 & 0xffffu), s3 = (int)(p1 >> 16);

        uint2 u0 = *(const uint2*)(g_hw + (size_t)s0 * DOUT + co);
        uint2 u1 = *(const uint2*)(g_hw + (size_t)s1 * DOUT + co);
        uint2 u2 = *(const uint2*)(g_hw + (size_t)s2 * DOUT + co);
        uint2 u3 = *(const uint2*)(g_hw + (size_t)s3 * DOUT + co);

        // fp16 pairwise tree: 4 rows -> 1 (noise ~2e-4 rel, see analysis)
        __half2 x01 = __hadd2(*(__half2*)&u0.x, *(__half2*)&u1.x);
        __half2 x23 = __hadd2(*(__half2*)&u2.x, *(__half2*)&u3.x);
        __half2 xs  = __hadd2(x01, x23);
        __half2 y01 = __hadd2(*(__half2*)&u0.y, *(__half2*)&u1.y);
        __half2 y23 = __hadd2(*(__half2*)&u2.y, *(__half2*)&u3.y);
        __half2 ys  = __hadd2(y01, y23);

        float2 fx = __half22float2(xs);
        float2 fy = __half22float2(ys);
        acc.x += fx.x; acc.y += fx.y; acc.z += fy.x; acc.w += fy.y;
    }
    // remainder: exact fp32 path
    for (; i < n; i++) {
        uint32_t p = __shfl_sync(0xffffffffu, packed, i >> 1);
        int s0 = (int)((i & 1) ? (p >> 16) : (p & 0xffffu));
        uint2 u = *(const uint2*)(g_hw + (size_t)s0 * DOUT + co);
        float2 a = __half22float2(*(__half2*)&u.x);
        float2 b = __half22float2(*(__half2*)&u.y);
        acc.x += a.x; acc.y += a.y; acc.z += b.x; acc.w += b.y;
    }

    if (cnt_raw > ELLW) {   // never in practice
        float4 ov = *(const float4*)(out + (size_t)d * DOUT + co);
        acc.x += ov.x; acc.y += ov.y; acc.z += ov.z; acc.w += ov.w;
    }

    float nr = __ldg(norm + d);
    float4 b = *(const float4*)(bias + co);
    float4 r;
    r.x = fmaxf(fmaf(acc.x, nr, b.x), 0.f);
    r.y = fmaxf(fmaf(acc.y, nr, b.y), 0.f);
    r.z = fmaxf(fmaf(acc.z, nr, b.z), 0.f);
    r.w = fmaxf(fmaf(acc.w, nr, b.w), 0.f);
    *(float4*)(out + (size_t)d * DOUT + co) = r;
}

// ---------------------------------------------------------------------------
// Launch. Input order (metadata): h, weight, bias, norm, src, dst
// ---------------------------------------------------------------------------
extern "C" void kernel_launch(void* const* d_in, const int* in_sizes, int n_in,
                              void* d_out, int out_size)
{
    const float* h    = (const float*)d_in[0];
    const float* W    = (const float*)d_in[1];
    const float* bias = (const float*)d_in[2];
    const float* norm = (const float*)d_in[3];
    const int*   src  = (const int*)d_in[4];
    const int*   dst  = (const int*)d_in[5];
    float*       out  = (float*)d_out;

    const int E = in_sizes[4];

    cudaFuncSetAttribute(gemm_mma_kernel,
                         cudaFuncAttributeMaxDynamicSharedMemorySize, SMEM_BYTES);

    // 0) convert h, W to fp16 globals; zero g_cnt
    prep_kernel<<<(NN * DIN / 4 + 255) / 256, 256>>>(h, W);

    // 1) projection -> fp16 g_hw (cp.async fills + fp16 mma)
    gemm_mma_kernel<<<(NN + 63) / 64, 128, SMEM_BYTES>>>(norm);

    // 2) build per-dst adjacency (ELL, u16)
    build_kernel<<<(E + 255) / 256, 256>>>(src, dst, out, E);

    // 3) gather-aggregate + fused norm/bias/relu (one warp per node)
    agg_kernel<<<(NN * 32 + 255) / 256, 256>>>(out, norm, bias);
}